// round 13
// baseline (speedup 1.0000x reference)
#include <cuda_runtime.h>
#include <cuda_bf16.h>
#include <cuda_fp16.h>
#include <cstdint>
#include <cstddef>

// Problem constants
#define NN     100000
#define NPAD   100096            // 782 * 128
#define NREL8  8
#define NRELT  16
#define DD     256
#define EE     262144            // 2^18
#define NTOT   (NRELT * DD)      // 4096
#define NB     (NRELT * NPAD)    // 1601536 bins
#define NBLK   (NB / 256)        // 6256
#define NCHUNK 4                 // pipeline chunks (4 relations each)
#define RELS_PER_CHUNK (NRELT / NCHUNK)

// GEMM tiling: A single fp16 tile + B hi/lo fp16 tiles, BK=64, 2 stages
#define STAGE  49152
#define A_T    0
#define B_HI   16384
#define B_LO   32768
#define SMEM_GEMM (2 * STAGE + 1024)

// ---------------- scratch (static device globals) --------------------------
__device__ __align__(16) __half g_Z[(size_t)NPAD * NTOT];           // 820 MB fp16
__device__ __align__(16) __half g_Xh[(size_t)NPAD * DD];            // X as fp16
__device__ __align__(16) __half g_Whi[(size_t)NTOT * DD];           // B^T: [n][k]
__device__ __align__(16) __half g_Wlo[(size_t)NTOT * DD];           // residual
__device__ int   g_degi[NB];
__device__ int   g_roff[NB];
__device__ int   g_cur[NB];
__device__ int   g_bsum[NBLK];
__device__ int   g_ecol[NRELT * EE];
__device__ float g_scale[NB];                // invfull[r] * invdeg_i[r]
__device__ float g_invfull[NPAD];
__device__ unsigned g_indmask[NPAD];
__device__ __align__(16) float g_bW[NRELT * DD];

// ---------------- helpers ---------------------------------------------------
__device__ __forceinline__ uint32_t sw128(uint32_t o) { return o ^ ((o >> 3) & 0x70); }
__device__ __forceinline__ uint32_t pack_h2(__half a, __half b) {
    return ((uint32_t)__half_as_ushort(b) << 16) | (uint32_t)__half_as_ushort(a);
}
__device__ __forceinline__ void cp16(uint32_t s, const void* g) {
    asm volatile("cp.async.cg.shared.global [%0], [%1], 16;"
                 :: "r"(s), "l"(__cvta_generic_to_global(g)) : "memory");
}
__device__ __forceinline__ void ldsm4(uint32_t r[4], uint32_t addr) {
    asm volatile("ldmatrix.sync.aligned.m8n8.x4.shared.b16 {%0,%1,%2,%3}, [%4];"
                 : "=r"(r[0]), "=r"(r[1]), "=r"(r[2]), "=r"(r[3]) : "r"(addr));
}
__device__ __forceinline__ void mma_fp16(float d[4], const uint32_t a[4],
                                         uint32_t b0, uint32_t b1) {
    asm volatile(
        "mma.sync.aligned.m16n8k16.row.col.f32.f16.f16.f32 "
        "{%0,%1,%2,%3}, {%4,%5,%6,%7}, {%8,%9}, {%0,%1,%2,%3};"
        : "+f"(d[0]), "+f"(d[1]), "+f"(d[2]), "+f"(d[3])
        : "r"(a[0]), "r"(a[1]), "r"(a[2]), "r"(a[3]), "r"(b0), "r"(b1));
}

// ---------------- CSR build --------------------------------------------------
__global__ void k_zdeg() {
    g_degi[blockIdx.x * blockDim.x + threadIdx.x] = 0;
}

__global__ void k_deg(const int* __restrict__ adj_row,
                      const int* __restrict__ adj_t_row) {
    int idx = blockIdx.x * blockDim.x + threadIdx.x;
    int rel = idx >> 18;
    int e   = idx & (EE - 1);
    int r = (rel < NREL8) ? __ldg(&adj_row[rel * EE + e])
                          : __ldg(&adj_t_row[(rel - NREL8) * EE + e]);
    atomicAdd(&g_degi[rel * NPAD + r], 1);
}

__global__ void k_scanA() {
    __shared__ int sh[256];
    int b = blockIdx.x, t = threadIdx.x;
    int v = g_degi[b * 256 + t];
    sh[t] = v; __syncthreads();
    #pragma unroll
    for (int o = 1; o < 256; o <<= 1) {
        int x = (t >= o) ? sh[t - o] : 0;
        __syncthreads();
        sh[t] += x;
        __syncthreads();
    }
    g_roff[b * 256 + t] = sh[t] - v;
    if (t == 255) g_bsum[b] = sh[255];
}

__global__ void k_scanB() {
    __shared__ int sh[256];
    __shared__ int run;
    int t = threadIdx.x;
    if (t == 0) run = 0;
    __syncthreads();
    for (int base = 0; base < NBLK; base += 256) {
        int idx = base + t;
        int v = (idx < NBLK) ? g_bsum[idx] : 0;
        sh[t] = v; __syncthreads();
        #pragma unroll
        for (int o = 1; o < 256; o <<= 1) {
            int x = (t >= o) ? sh[t - o] : 0;
            __syncthreads();
            sh[t] += x;
            __syncthreads();
        }
        if (idx < NBLK) g_bsum[idx] = run + sh[t] - v;
        __syncthreads();
        if (t == 255) run += sh[255];
        __syncthreads();
    }
}

__global__ void k_scanC() {
    int i = blockIdx.x * 256 + threadIdx.x;
    int v = g_roff[i] + g_bsum[i >> 8];
    g_roff[i] = v;
    g_cur[i]  = v;
}

__global__ void k_ecol(const int* __restrict__ adj_row, const int* __restrict__ adj_col,
                       const int* __restrict__ adj_t_row, const int* __restrict__ adj_t_col) {
    int idx = blockIdx.x * blockDim.x + threadIdx.x;
    int rel = idx >> 18;
    int e   = idx & (EE - 1);
    int r, c;
    if (rel < NREL8) {
        r = __ldg(&adj_row[rel * EE + e]);
        c = __ldg(&adj_col[rel * EE + e]);
    } else {
        int rr = rel - NREL8;
        r = __ldg(&adj_t_row[rr * EE + e]);
        c = __ldg(&adj_t_col[rr * EE + e]);
    }
    int pos = atomicAdd(&g_cur[rel * NPAD + r], 1);
    g_ecol[pos] = c;
}

// ---------------- norms / bias ------------------------------------------------
__global__ void k_norm() {
    int m = blockIdx.x * blockDim.x + threadIdx.x;
    if (m >= NPAD) return;
    float full = 0.f;
    unsigned mask = 0;
    float inv[NRELT];
    #pragma unroll
    for (int i = 0; i < NRELT; i++) {
        int d = g_degi[i * NPAD + m];
        if (d > 0) { full += 1.f; mask |= (1u << i); inv[i] = 1.f / (float)d; }
        else inv[i] = 1.f;
    }
    float invf = (full > 0.f) ? (1.f / full) : 1.f;
    g_invfull[m] = invf;
    g_indmask[m] = mask;
    #pragma unroll
    for (int i = 0; i < NRELT; i++) g_scale[i * NPAD + m] = invf * inv[i];
}

__global__ void k_bw(const float* __restrict__ bias, const float* __restrict__ w,
                     const float* __restrict__ bias_t, const float* __restrict__ w_t) {
    int i = blockIdx.x;
    int n = threadIdx.x;
    const float* b = (i < NREL8) ? (bias + i * DD) : (bias_t + (i - NREL8) * DD);
    const float* W = (i < NREL8) ? (w + (size_t)i * DD * DD)
                                 : (w_t + (size_t)(i - NREL8) * DD * DD);
    float s = 0.f;
    for (int k = 0; k < DD; k++) s += b[k] * W[(size_t)k * DD + n];
    g_bW[i * DD + n] = s;
}

// Split W into fp16 hi/lo, B^T layout: g_Whi[(rel*256+c)*256 + k] = W_rel[k][c]
__global__ void k_prepW(const float* __restrict__ w, const float* __restrict__ w_t) {
    int idx = blockIdx.x * blockDim.x + threadIdx.x;   // NTOT*DD = 1048576
    int k   = idx & 255;
    int n   = idx >> 8;
    int rel = n >> 8;
    int c   = n & 255;
    const float* W = (rel < NREL8) ? (w + (size_t)rel * DD * DD)
                                   : (w_t + (size_t)(rel - NREL8) * DD * DD);
    float x = W[(size_t)k * DD + c];
    __half h = __float2half(x);
    g_Whi[idx] = h;
    g_Wlo[idx] = __float2half(x - __half2float(h));
}

// Convert X to fp16 (single term); pad rows -> 0
__global__ void k_prepX(const float* __restrict__ feat) {
    int idx = blockIdx.x * blockDim.x + threadIdx.x;   // NPAD*64 (float4 units)
    int m = idx >> 6;
    float4 v = make_float4(0.f, 0.f, 0.f, 0.f);
    if (m < NN) v = reinterpret_cast<const float4*>(feat)[idx];
    uint2 hp;
    hp.x = pack_h2(__float2half(v.x), __float2half(v.y));
    hp.y = pack_h2(__float2half(v.z), __float2half(v.w));
    reinterpret_cast<uint2*>(g_Xh)[idx] = hp;
}

// out[m][:] = invfull[m] * sum_{i: deg_i[m]>0} bW_i[:]  (bias base; gather adds)
__global__ void k_init(float* __restrict__ out) {
    __shared__ float4 bws[NRELT * 64];
    int tid = threadIdx.x;
    for (int x = tid; x < NRELT * 64; x += 256)
        bws[x] = reinterpret_cast<const float4*>(g_bW)[x];
    __syncthreads();
    int idx = blockIdx.x * 256 + tid;       // NN*64 exactly
    int m = idx >> 6, q = idx & 63;
    unsigned mask = g_indmask[m];
    float invf = g_invfull[m];
    float4 s = make_float4(0.f, 0.f, 0.f, 0.f);
    #pragma unroll
    for (int i = 0; i < NRELT; i++) {
        if ((mask >> i) & 1u) {
            float4 b = bws[i * 64 + q];
            s.x += b.x; s.y += b.y; s.z += b.z; s.w += b.w;
        }
    }
    s.x *= invf; s.y *= invf; s.z *= invf; s.w *= invf;
    reinterpret_cast<float4*>(out)[idx] = s;
}

// ---------------- GEMM: Z = Xh @ (Whi + Wlo), 2-term fp16 via mma.sync --------
// One launch covers columns [col0, col0 + 1024) = 4 relations.
__device__ __forceinline__ void load_stage(uint32_t sb, int tid, int rowBase,
                                           int colBase, int kb) {
    #pragma unroll
    for (int p = 0; p < 4; p++) {
        int idx = tid + p * 256;
        int row = idx >> 3, ch = idx & 7;
        uint32_t so = sw128(row * 128 + ch * 16);
        size_t ga = (size_t)(rowBase + row) * DD + kb + ch * 8;
        size_t gb = (size_t)(colBase + row) * DD + kb + ch * 8;
        cp16(sb + A_T + so, g_Xh + ga);
        cp16(sb + B_HI + so, g_Whi + gb);
        cp16(sb + B_LO + so, g_Wlo + gb);
    }
    asm volatile("cp.async.commit_group;" ::: "memory");
}

__global__ void __launch_bounds__(256, 2) k_gemm(int col0) {
    extern __shared__ char smraw[];
    uint32_t sraw = (uint32_t)__cvta_generic_to_shared(smraw);
    uint32_t sbase = (sraw + 1023) & ~1023u;

    const int tid = threadIdx.x;
    const int lane = tid & 31;
    const int wid = tid >> 5;
    const int wm = wid >> 1;          // 0..3 (M dir, 32 rows each)
    const int wn = wid & 1;           // 0..1 (N dir, 64 cols each)
    const int rowBase = blockIdx.y * 128;
    const int colBase = col0 + blockIdx.x * 128;

    float acc[2][8][4] = {};

    uint32_t aoff[2], boff[4];
    #pragma unroll
    for (int mf = 0; mf < 2; mf++)
        aoff[mf] = sw128((wm * 32 + mf * 16 + (lane & 15)) * 128 + (lane >> 4) * 16);
    #pragma unroll
    for (int nf = 0; nf < 4; nf++)
        boff[nf] = sw128((wn * 64 + nf * 16 + (lane & 15)) * 128 + (lane >> 4) * 16);

    load_stage(sbase, tid, rowBase, colBase, 0);

    #pragma unroll
    for (int t = 0; t < 4; t++) {
        asm volatile("cp.async.wait_group 0;" ::: "memory");
        __syncthreads();
        if (t < 3) load_stage(sbase + ((t + 1) & 1) * STAGE, tid, rowBase, colBase, (t + 1) * 64);
        uint32_t sb = sbase + (t & 1) * STAGE;

        #pragma unroll
        for (int ks = 0; ks < 4; ks++) {
            // ks*32 hits the swizzle's XOR-target bits [5:6] -> compose with XOR.
            uint32_t kx = ks * 32;
            uint32_t ah[2][4], bh[4][4], bl[4][4];
            #pragma unroll
            for (int mf = 0; mf < 2; mf++)
                ldsm4(ah[mf], sb + A_T + (aoff[mf] ^ kx));
            #pragma unroll
            for (int nf = 0; nf < 4; nf++) {
                uint32_t o = boff[nf] ^ kx;
                ldsm4(bh[nf], sb + B_HI + o);
                ldsm4(bl[nf], sb + B_LO + o);
            }
            #pragma unroll
            for (int mf = 0; mf < 2; mf++) {
                #pragma unroll
                for (int j = 0; j < 8; j++) {
                    uint32_t b0h = bh[j >> 1][j & 1], b1h = bh[j >> 1][(j & 1) + 2];
                    uint32_t b0l = bl[j >> 1][j & 1], b1l = bl[j >> 1][(j & 1) + 2];
                    mma_fp16(acc[mf][j], ah[mf], b0h, b1h);   // A * Bhi
                    mma_fp16(acc[mf][j], ah[mf], b0l, b1l);   // A * Blo
                }
            }
        }
    }

    // Epilogue: store Z as fp16 (half2 pairs; cc is even -> 4B aligned)
    __half* Zb = g_Z + (size_t)(rowBase + wm * 32) * NTOT + colBase + wn * 64;
    #pragma unroll
    for (int mf = 0; mf < 2; mf++) {
        #pragma unroll
        for (int j = 0; j < 8; j++) {
            int r = mf * 16 + (lane >> 2);
            int cc = j * 8 + (lane & 3) * 2;
            __half2 v0 = __floats2half2_rn(acc[mf][j][0], acc[mf][j][1]);
            __half2 v1 = __floats2half2_rn(acc[mf][j][2], acc[mf][j][3]);
            *reinterpret_cast<__half2*>(Zb + (size_t)r * NTOT + cc) = v0;
            *reinterpret_cast<__half2*>(Zb + (size_t)(r + 8) * NTOT + cc) = v1;
        }
    }
}

// ---------------- CSR gather chunk: rels [rel0, rel0+4), one warp per row -----
__global__ void __launch_bounds__(256) k_gather(int rel0, float* __restrict__ out) {
    unsigned gw = ((unsigned)blockIdx.x * blockDim.x + threadIdx.x) >> 5;
    int lane = threadIdx.x & 31;
    if (gw >= NN) return;
    int row = (int)gw;

    float4* outv = reinterpret_cast<float4*>(out);
    float4 a0 = outv[(size_t)row * 64 + lane];        // cols 4*lane..4*lane+3
    float4 a1 = outv[(size_t)row * 64 + lane + 32];   // cols 128+4*lane..

    #pragma unroll 1
    for (int rel = rel0; rel < rel0 + RELS_PER_CHUNK; rel++) {
        int bin = rel * NPAD + row;
        int d = g_degi[bin];
        if (d == 0) continue;
        int s0 = g_roff[bin];
        float s = g_scale[bin];
        const __half* zb = g_Z + rel * DD;
        #pragma unroll 2
        for (int j = 0; j < d; j++) {
            int c = __ldg(&g_ecol[s0 + j]);
            const uint2* zp = reinterpret_cast<const uint2*>(zb + (size_t)c * NTOT);
            uint2 r0 = __ldg(zp + lane);
            uint2 r1 = __ldg(zp + lane + 32);
            float2 q0 = __half22float2(*reinterpret_cast<__half2*>(&r0.x));
            float2 q1 = __half22float2(*reinterpret_cast<__half2*>(&r0.y));
            float2 q2 = __half22float2(*reinterpret_cast<__half2*>(&r1.x));
            float2 q3 = __half22float2(*reinterpret_cast<__half2*>(&r1.y));
            a0.x += s * q0.x; a0.y += s * q0.y; a0.z += s * q1.x; a0.w += s * q1.y;
            a1.x += s * q2.x; a1.y += s * q2.y; a1.z += s * q3.x; a1.w += s * q3.y;
        }
    }
    outv[(size_t)row * 64 + lane] = a0;
    outv[(size_t)row * 64 + lane + 32] = a1;
}

// ---------------- launch: GEMM/gather software pipeline ------------------------
extern "C" void kernel_launch(void* const* d_in, const int* in_sizes, int n_in,
                              void* d_out, int out_size) {
    const float* features  = (const float*)d_in[0];
    const float* w         = (const float*)d_in[1];
    const float* bias      = (const float*)d_in[2];
    const float* w_t       = (const float*)d_in[3];
    const float* bias_t    = (const float*)d_in[4];
    const int*   adj_row   = (const int*)d_in[5];
    const int*   adj_col   = (const int*)d_in[6];
    const int*   adj_t_row = (const int*)d_in[7];
    const int*   adj_t_col = (const int*)d_in[8];
    float* out = (float*)d_out;

    static cudaStream_t s1;
    static cudaEvent_t evFork, evG[NCHUNK], evDone;
    static bool init_done = false;
    if (!init_done) {
        cudaFuncSetAttribute(k_gemm, cudaFuncAttributeMaxDynamicSharedMemorySize, SMEM_GEMM);
        cudaStreamCreateWithFlags(&s1, cudaStreamNonBlocking);
        cudaEventCreateWithFlags(&evFork, cudaEventDisableTiming);
        for (int g = 0; g < NCHUNK; g++)
            cudaEventCreateWithFlags(&evG[g], cudaEventDisableTiming);
        cudaEventCreateWithFlags(&evDone, cudaEventDisableTiming);
        init_done = true;
    }

    // fork side stream
    cudaEventRecord(evFork, 0);
    cudaStreamWaitEvent(s1, evFork, 0);

    // Chain B (CSR/norm/bias/init) on s1 — overlaps prep + first GEMM chunks.
    k_zdeg<<<NB / 256, 256, 0, s1>>>();
    k_deg<<<(NRELT * EE) / 256, 256, 0, s1>>>(adj_row, adj_t_row);
    k_scanA<<<NBLK, 256, 0, s1>>>();
    k_scanB<<<1, 256, 0, s1>>>();
    k_scanC<<<NBLK, 256, 0, s1>>>();
    k_ecol<<<(NRELT * EE) / 256, 256, 0, s1>>>(adj_row, adj_col, adj_t_row, adj_t_col);
    k_norm<<<(NPAD + 255) / 256, 256, 0, s1>>>();
    k_bw<<<NRELT, 256, 0, s1>>>(bias, w, bias_t, w_t);
    k_init<<<(NN * 64) / 256, 256, 0, s1>>>(out);

    // Chain A: prep, then GEMM chunks (4 relations = 1024 Z columns each).
    k_prepX<<<(NPAD * 64) / 256, 256>>>(features);
    k_prepW<<<(NTOT * DD) / 256, 256>>>(w, w_t);
    for (int g = 0; g < NCHUNK; g++) {
        k_gemm<<<dim3(RELS_PER_CHUNK * 2, NPAD / 128), 256, SMEM_GEMM>>>(g * RELS_PER_CHUNK * DD);
        cudaEventRecord(evG[g], 0);
    }

    // Gather chunks on s1: serialized among themselves (no out race),
    // chunk g waits only on its GEMM chunk -> overlaps later GEMM chunks.
    for (int g = 0; g < NCHUNK; g++) {
        cudaStreamWaitEvent(s1, evG[g], 0);
        k_gather<<<(NN * 32 + 255) / 256, 256, 0, s1>>>(g * RELS_PER_CHUNK, out);
    }
    cudaEventRecord(evDone, s1);

    // join back to origin stream
    cudaStreamWaitEvent(0, evDone, 0);
}

// round 14
// speedup vs baseline: 1.4041x; 1.4041x over previous
#include <cuda_runtime.h>
#include <cuda_bf16.h>
#include <cuda_fp16.h>
#include <cstdint>
#include <cstddef>

// Problem constants
#define NN     100000
#define NPAD   100096            // 782 * 128
#define NREL8  8
#define NRELT  16
#define DD     256
#define EE     262144            // 2^18
#define NTOT   (NRELT * DD)      // 4096
#define NB     (NRELT * NPAD)    // 1601536 bins
#define NBLK   (NB / 256)        // 6256

// GEMM tiling: A fp16 tile + B fp16 tile (single term), BK=64, 2 stages
#define STAGE  32768
#define A_T    0
#define B_T    16384
#define SMEM_GEMM (2 * STAGE + 1024)

// ---------------- scratch (static device globals) --------------------------
__device__ __align__(16) __half g_Z[(size_t)NPAD * NTOT];           // 820 MB fp16
__device__ __align__(16) __half g_Xh[(size_t)NPAD * DD];            // X as fp16
__device__ __align__(16) __half g_Wh[(size_t)NTOT * DD];            // B^T: [n][k] fp16
__device__ int   g_degi[NB];
__device__ int   g_roff[NB];
__device__ int   g_cur[NB];
__device__ int   g_bsum[NBLK];
__device__ int   g_ecol[NRELT * EE];
__device__ float g_scale[NB];                // invfull[r] * invdeg_i[r]
__device__ float g_invfull[NPAD];
__device__ unsigned g_indmask[NPAD];
__device__ __align__(16) float g_bW[NRELT * DD];

// ---------------- helpers ---------------------------------------------------
__device__ __forceinline__ uint32_t sw128(uint32_t o) { return o ^ ((o >> 3) & 0x70); }
__device__ __forceinline__ uint32_t pack_h2(__half a, __half b) {
    return ((uint32_t)__half_as_ushort(b) << 16) | (uint32_t)__half_as_ushort(a);
}
__device__ __forceinline__ void cp16(uint32_t s, const void* g) {
    asm volatile("cp.async.cg.shared.global [%0], [%1], 16;"
                 :: "r"(s), "l"(__cvta_generic_to_global(g)) : "memory");
}
__device__ __forceinline__ void ldsm4(uint32_t r[4], uint32_t addr) {
    asm volatile("ldmatrix.sync.aligned.m8n8.x4.shared.b16 {%0,%1,%2,%3}, [%4];"
                 : "=r"(r[0]), "=r"(r[1]), "=r"(r[2]), "=r"(r[3]) : "r"(addr));
}
__device__ __forceinline__ void mma_fp16(float d[4], const uint32_t a[4],
                                         uint32_t b0, uint32_t b1) {
    asm volatile(
        "mma.sync.aligned.m16n8k16.row.col.f32.f16.f16.f32 "
        "{%0,%1,%2,%3}, {%4,%5,%6,%7}, {%8,%9}, {%0,%1,%2,%3};"
        : "+f"(d[0]), "+f"(d[1]), "+f"(d[2]), "+f"(d[3])
        : "r"(a[0]), "r"(a[1]), "r"(a[2]), "r"(a[3]), "r"(b0), "r"(b1));
}

// ---------------- CSR build --------------------------------------------------
__global__ void k_zdeg() {
    g_degi[blockIdx.x * blockDim.x + threadIdx.x] = 0;
}

__global__ void k_deg(const int* __restrict__ adj_row,
                      const int* __restrict__ adj_t_row) {
    int idx = blockIdx.x * blockDim.x + threadIdx.x;
    int rel = idx >> 18;
    int e   = idx & (EE - 1);
    int r = (rel < NREL8) ? __ldg(&adj_row[rel * EE + e])
                          : __ldg(&adj_t_row[(rel - NREL8) * EE + e]);
    atomicAdd(&g_degi[rel * NPAD + r], 1);
}

__global__ void k_scanA() {
    __shared__ int sh[256];
    int b = blockIdx.x, t = threadIdx.x;
    int v = g_degi[b * 256 + t];
    sh[t] = v; __syncthreads();
    #pragma unroll
    for (int o = 1; o < 256; o <<= 1) {
        int x = (t >= o) ? sh[t - o] : 0;
        __syncthreads();
        sh[t] += x;
        __syncthreads();
    }
    g_roff[b * 256 + t] = sh[t] - v;
    if (t == 255) g_bsum[b] = sh[255];
}

__global__ void k_scanB() {
    __shared__ int sh[256];
    __shared__ int run;
    int t = threadIdx.x;
    if (t == 0) run = 0;
    __syncthreads();
    for (int base = 0; base < NBLK; base += 256) {
        int idx = base + t;
        int v = (idx < NBLK) ? g_bsum[idx] : 0;
        sh[t] = v; __syncthreads();
        #pragma unroll
        for (int o = 1; o < 256; o <<= 1) {
            int x = (t >= o) ? sh[t - o] : 0;
            __syncthreads();
            sh[t] += x;
            __syncthreads();
        }
        if (idx < NBLK) g_bsum[idx] = run + sh[t] - v;
        __syncthreads();
        if (t == 255) run += sh[255];
        __syncthreads();
    }
}

__global__ void k_scanC() {
    int i = blockIdx.x * 256 + threadIdx.x;
    int v = g_roff[i] + g_bsum[i >> 8];
    g_roff[i] = v;
    g_cur[i]  = v;
}

__global__ void k_ecol(const int* __restrict__ adj_row, const int* __restrict__ adj_col,
                       const int* __restrict__ adj_t_row, const int* __restrict__ adj_t_col) {
    int idx = blockIdx.x * blockDim.x + threadIdx.x;
    int rel = idx >> 18;
    int e   = idx & (EE - 1);
    int r, c;
    if (rel < NREL8) {
        r = __ldg(&adj_row[rel * EE + e]);
        c = __ldg(&adj_col[rel * EE + e]);
    } else {
        int rr = rel - NREL8;
        r = __ldg(&adj_t_row[rr * EE + e]);
        c = __ldg(&adj_t_col[rr * EE + e]);
    }
    int pos = atomicAdd(&g_cur[rel * NPAD + r], 1);
    g_ecol[pos] = c;
}

// ---------------- norms / bias ------------------------------------------------
__global__ void k_norm() {
    int m = blockIdx.x * blockDim.x + threadIdx.x;
    if (m >= NPAD) return;
    float full = 0.f;
    unsigned mask = 0;
    float inv[NRELT];
    #pragma unroll
    for (int i = 0; i < NRELT; i++) {
        int d = g_degi[i * NPAD + m];
        if (d > 0) { full += 1.f; mask |= (1u << i); inv[i] = 1.f / (float)d; }
        else inv[i] = 1.f;
    }
    float invf = (full > 0.f) ? (1.f / full) : 1.f;
    g_invfull[m] = invf;
    g_indmask[m] = mask;
    #pragma unroll
    for (int i = 0; i < NRELT; i++) g_scale[i * NPAD + m] = invf * inv[i];
}

__global__ void k_bw(const float* __restrict__ bias, const float* __restrict__ w,
                     const float* __restrict__ bias_t, const float* __restrict__ w_t) {
    int i = blockIdx.x;
    int n = threadIdx.x;
    const float* b = (i < NREL8) ? (bias + i * DD) : (bias_t + (i - NREL8) * DD);
    const float* W = (i < NREL8) ? (w + (size_t)i * DD * DD)
                                 : (w_t + (size_t)(i - NREL8) * DD * DD);
    float s = 0.f;
    for (int k = 0; k < DD; k++) s += b[k] * W[(size_t)k * DD + n];
    g_bW[i * DD + n] = s;
}

// W to fp16 (single term), B^T layout: g_Wh[(rel*256+c)*256 + k] = W_rel[k][c]
__global__ void k_prepW(const float* __restrict__ w, const float* __restrict__ w_t) {
    int idx = blockIdx.x * blockDim.x + threadIdx.x;   // NTOT*DD = 1048576
    int k   = idx & 255;
    int n   = idx >> 8;
    int rel = n >> 8;
    int c   = n & 255;
    const float* W = (rel < NREL8) ? (w + (size_t)rel * DD * DD)
                                   : (w_t + (size_t)(rel - NREL8) * DD * DD);
    g_Wh[idx] = __float2half(W[(size_t)k * DD + c]);
}

// Convert X to fp16 (single term); pad rows -> 0
__global__ void k_prepX(const float* __restrict__ feat) {
    int idx = blockIdx.x * blockDim.x + threadIdx.x;   // NPAD*64 (float4 units)
    int m = idx >> 6;
    float4 v = make_float4(0.f, 0.f, 0.f, 0.f);
    if (m < NN) v = reinterpret_cast<const float4*>(feat)[idx];
    uint2 hp;
    hp.x = pack_h2(__float2half(v.x), __float2half(v.y));
    hp.y = pack_h2(__float2half(v.z), __float2half(v.w));
    reinterpret_cast<uint2*>(g_Xh)[idx] = hp;
}

// out[m][:] = invfull[m] * sum_{i: deg_i[m]>0} bW_i[:]  (bias base; gather adds)
__global__ void k_init(float* __restrict__ out) {
    __shared__ float4 bws[NRELT * 64];
    int tid = threadIdx.x;
    for (int x = tid; x < NRELT * 64; x += 256)
        bws[x] = reinterpret_cast<const float4*>(g_bW)[x];
    __syncthreads();
    int idx = blockIdx.x * 256 + tid;       // NN*64 exactly
    int m = idx >> 6, q = idx & 63;
    unsigned mask = g_indmask[m];
    float invf = g_invfull[m];
    float4 s = make_float4(0.f, 0.f, 0.f, 0.f);
    #pragma unroll
    for (int i = 0; i < NRELT; i++) {
        if ((mask >> i) & 1u) {
            float4 b = bws[i * 64 + q];
            s.x += b.x; s.y += b.y; s.z += b.z; s.w += b.w;
        }
    }
    s.x *= invf; s.y *= invf; s.z *= invf; s.w *= invf;
    reinterpret_cast<float4*>(out)[idx] = s;
}

// ---------------- GEMM: Z = Xh @ Wh, single-term fp16 via mma.sync ------------
__device__ __forceinline__ void load_stage(uint32_t sb, int tid, int rowBase,
                                           int colBase, int kb) {
    #pragma unroll
    for (int p = 0; p < 4; p++) {
        int idx = tid + p * 256;
        int row = idx >> 3, ch = idx & 7;
        uint32_t so = sw128(row * 128 + ch * 16);
        size_t ga = (size_t)(rowBase + row) * DD + kb + ch * 8;
        size_t gb = (size_t)(colBase + row) * DD + kb + ch * 8;
        cp16(sb + A_T + so, g_Xh + ga);
        cp16(sb + B_T + so, g_Wh + gb);
    }
    asm volatile("cp.async.commit_group;" ::: "memory");
}

__global__ void __launch_bounds__(256, 2) k_gemm() {
    extern __shared__ char smraw[];
    uint32_t sraw = (uint32_t)__cvta_generic_to_shared(smraw);
    uint32_t sbase = (sraw + 1023) & ~1023u;

    const int tid = threadIdx.x;
    const int lane = tid & 31;
    const int wid = tid >> 5;
    const int wm = wid >> 1;          // 0..3 (M dir, 32 rows each)
    const int wn = wid & 1;           // 0..1 (N dir, 64 cols each)
    const int rowBase = blockIdx.y * 128;
    const int colBase = blockIdx.x * 128;

    float acc[2][8][4] = {};

    uint32_t aoff[2], boff[4];
    #pragma unroll
    for (int mf = 0; mf < 2; mf++)
        aoff[mf] = sw128((wm * 32 + mf * 16 + (lane & 15)) * 128 + (lane >> 4) * 16);
    #pragma unroll
    for (int nf = 0; nf < 4; nf++)
        boff[nf] = sw128((wn * 64 + nf * 16 + (lane & 15)) * 128 + (lane >> 4) * 16);

    load_stage(sbase, tid, rowBase, colBase, 0);

    #pragma unroll
    for (int t = 0; t < 4; t++) {
        asm volatile("cp.async.wait_group 0;" ::: "memory");
        __syncthreads();
        if (t < 3) load_stage(sbase + ((t + 1) & 1) * STAGE, tid, rowBase, colBase, (t + 1) * 64);
        uint32_t sb = sbase + (t & 1) * STAGE;

        #pragma unroll
        for (int ks = 0; ks < 4; ks++) {
            // ks*32 hits the swizzle's XOR-target bits [5:6] -> compose with XOR.
            uint32_t kx = ks * 32;
            uint32_t ah[2][4], bh[4][4];
            #pragma unroll
            for (int mf = 0; mf < 2; mf++)
                ldsm4(ah[mf], sb + A_T + (aoff[mf] ^ kx));
            #pragma unroll
            for (int nf = 0; nf < 4; nf++)
                ldsm4(bh[nf], sb + B_T + (boff[nf] ^ kx));
            #pragma unroll
            for (int mf = 0; mf < 2; mf++) {
                #pragma unroll
                for (int j = 0; j < 8; j++) {
                    uint32_t b0 = bh[j >> 1][j & 1], b1 = bh[j >> 1][(j & 1) + 2];
                    mma_fp16(acc[mf][j], ah[mf], b0, b1);
                }
            }
        }
    }

    // Epilogue: store Z as fp16 (half2 pairs; cc is even -> 4B aligned)
    __half* Zb = g_Z + (size_t)(rowBase + wm * 32) * NTOT + colBase + wn * 64;
    #pragma unroll
    for (int mf = 0; mf < 2; mf++) {
        #pragma unroll
        for (int j = 0; j < 8; j++) {
            int r = mf * 16 + (lane >> 2);
            int cc = j * 8 + (lane & 3) * 2;
            __half2 v0 = __floats2half2_rn(acc[mf][j][0], acc[mf][j][1]);
            __half2 v1 = __floats2half2_rn(acc[mf][j][2], acc[mf][j][3]);
            *reinterpret_cast<__half2*>(Zb + (size_t)r * NTOT + cc) = v0;
            *reinterpret_cast<__half2*>(Zb + (size_t)(r + 8) * NTOT + cc) = v1;
        }
    }
}

// ---------------- CSR gather: one warp owns one output row (no atomics) -------
__global__ void __launch_bounds__(256) k_gather(float* __restrict__ out) {
    unsigned gw = ((unsigned)blockIdx.x * blockDim.x + threadIdx.x) >> 5;
    int lane = threadIdx.x & 31;
    if (gw >= NN) return;
    int row = (int)gw;

    float4* outv = reinterpret_cast<float4*>(out);
    float4 a0 = outv[(size_t)row * 64 + lane];        // cols 4*lane..4*lane+3
    float4 a1 = outv[(size_t)row * 64 + lane + 32];   // cols 128+4*lane..

    #pragma unroll 1
    for (int rel = 0; rel < NRELT; rel++) {
        int bin = rel * NPAD + row;
        int d = g_degi[bin];
        if (d == 0) continue;
        int s0 = g_roff[bin];
        float s = g_scale[bin];
        const __half* zb = g_Z + rel * DD;
        #pragma unroll 2
        for (int j = 0; j < d; j++) {
            int c = __ldg(&g_ecol[s0 + j]);
            const uint2* zp = reinterpret_cast<const uint2*>(zb + (size_t)c * NTOT);
            uint2 r0 = __ldg(zp + lane);
            uint2 r1 = __ldg(zp + lane + 32);
            float2 q0 = __half22float2(*reinterpret_cast<__half2*>(&r0.x));
            float2 q1 = __half22float2(*reinterpret_cast<__half2*>(&r0.y));
            float2 q2 = __half22float2(*reinterpret_cast<__half2*>(&r1.x));
            float2 q3 = __half22float2(*reinterpret_cast<__half2*>(&r1.y));
            a0.x += s * q0.x; a0.y += s * q0.y; a0.z += s * q1.x; a0.w += s * q1.y;
            a1.x += s * q2.x; a1.y += s * q2.y; a1.z += s * q3.x; a1.w += s * q3.y;
        }
    }
    outv[(size_t)row * 64 + lane] = a0;
    outv[(size_t)row * 64 + lane + 32] = a1;
}

// ---------------- launch: fork CSR chain onto a side stream (R12 structure) ----
extern "C" void kernel_launch(void* const* d_in, const int* in_sizes, int n_in,
                              void* d_out, int out_size) {
    const float* features  = (const float*)d_in[0];
    const float* w         = (const float*)d_in[1];
    const float* bias      = (const float*)d_in[2];
    const float* w_t       = (const float*)d_in[3];
    const float* bias_t    = (const float*)d_in[4];
    const int*   adj_row   = (const int*)d_in[5];
    const int*   adj_col   = (const int*)d_in[6];
    const int*   adj_t_row = (const int*)d_in[7];
    const int*   adj_t_col = (const int*)d_in[8];
    float* out = (float*)d_out;

    static cudaStream_t s1;
    static cudaEvent_t evFork, evJoin;
    static bool init_done = false;
    if (!init_done) {
        cudaFuncSetAttribute(k_gemm, cudaFuncAttributeMaxDynamicSharedMemorySize, SMEM_GEMM);
        cudaStreamCreateWithFlags(&s1, cudaStreamNonBlocking);
        cudaEventCreateWithFlags(&evFork, cudaEventDisableTiming);
        cudaEventCreateWithFlags(&evJoin, cudaEventDisableTiming);
        init_done = true;
    }

    // fork: side stream joins the captured graph
    cudaEventRecord(evFork, 0);
    cudaStreamWaitEvent(s1, evFork, 0);

    // Chain B (CSR/norm/bias/init) on s1.
    k_zdeg<<<NB / 256, 256, 0, s1>>>();
    k_deg<<<(NRELT * EE) / 256, 256, 0, s1>>>(adj_row, adj_t_row);
    k_scanA<<<NBLK, 256, 0, s1>>>();
    k_scanB<<<1, 256, 0, s1>>>();
    k_scanC<<<NBLK, 256, 0, s1>>>();
    k_ecol<<<(NRELT * EE) / 256, 256, 0, s1>>>(adj_row, adj_col, adj_t_row, adj_t_col);
    k_norm<<<(NPAD + 255) / 256, 256, 0, s1>>>();
    k_bw<<<NRELT, 256, 0, s1>>>(bias, w, bias_t, w_t);
    k_init<<<(NN * 64) / 256, 256, 0, s1>>>(out);
    cudaEventRecord(evJoin, s1);

    // Chain A (compute) on the origin stream.
    k_prepX<<<(NPAD * 64) / 256, 256>>>(features);
    k_prepW<<<(NTOT * DD) / 256, 256>>>(w, w_t);
    k_gemm<<<dim3(NTOT / 128, NPAD / 128), 256, SMEM_GEMM>>>();

    // join, then gather
    cudaStreamWaitEvent(0, evJoin, 0);
    k_gather<<<(NN * 32) / 256, 256>>>(out);
}